// round 2
// baseline (speedup 1.0000x reference)
#include <cuda_runtime.h>
#include <cuda_bf16.h>

// Problem constants
#define Bc 2
#define Lc 4096
#define Hc 8
#define Dc 64
#define Mc 128
#define BH 16          // B*H
#define CH 64          // chunk length
#define NCH 64         // number of chunks per (b,h)
#define NROWS (Bc*Lc*Hc)   // 65536

// Scratch (device globals; no allocation allowed)
__device__ float g_qp[BH * Lc * Mc];            // [bh][l][m]
__device__ float g_kp[BH * Lc * Mc];            // [bh][l][m]
__device__ float g_state[BH * NCH * Dc * Mc];   // per chunk: [d][m] (d-major), becomes exclusive prefix
__device__ float g_ksum[BH * NCH * Mc];         // per chunk: [m], becomes exclusive prefix

// ---------------------------------------------------------------------------
// Kernel 1: projection + relu + eps.  grid (2048, 2): y=0 -> query, y=1 -> key
// Each block: 32 input rows, all 128 outputs.
// ---------------------------------------------------------------------------
__global__ void proj_kernel(const float* __restrict__ qg,
                            const float* __restrict__ kg,
                            const float* __restrict__ pg)
{
    __shared__ float p_s[128 * 65];   // proj [m][d], pitch 65 (odd -> conflict free)
    __shared__ float row_s[32 * 64];  // input rows

    const float* inp  = blockIdx.y ? kg : qg;
    float*       outp = blockIdx.y ? g_kp : g_qp;

    int tid = threadIdx.x;

    // load projection matrix (8192 floats)
    const float4* p4 = (const float4*)pg;
    #pragma unroll
    for (int t = tid; t < 2048; t += 256) {
        float4 v = p4[t];
        int m = t >> 4;            // 16 float4 per 64-wide row
        int d = (t & 15) * 4;
        float* dst = &p_s[m * 65 + d];
        dst[0] = v.x; dst[1] = v.y; dst[2] = v.z; dst[3] = v.w;
    }

    // load 32 rows (rows are contiguous in [B*L*H, 64])
    int rowbase = blockIdx.x * 32;
    const float4* in4 = (const float4*)(inp + (size_t)rowbase * 64);
    float4* rs4 = (float4*)row_s;
    rs4[tid]       = in4[tid];
    rs4[tid + 256] = in4[tid + 256];
    __syncthreads();

    int mg = tid & 31;     // m = mg + 32*i  (lane-consecutive -> conflict free)
    int rg = tid >> 5;     // 8 groups of 4 rows
    int r0 = rg * 4;

    float acc[4][4];
    #pragma unroll
    for (int r = 0; r < 4; r++)
        #pragma unroll
        for (int i = 0; i < 4; i++) acc[r][i] = 0.f;

    #pragma unroll 8
    for (int d = 0; d < 64; d++) {
        float pv[4], rv[4];
        #pragma unroll
        for (int i = 0; i < 4; i++) pv[i] = p_s[(mg + 32 * i) * 65 + d];
        #pragma unroll
        for (int r = 0; r < 4; r++) rv[r] = row_s[(r0 + r) * 64 + d];   // broadcast
        #pragma unroll
        for (int r = 0; r < 4; r++)
            #pragma unroll
            for (int i = 0; i < 4; i++)
                acc[r][i] = fmaf(rv[r], pv[i], acc[r][i]);
    }

    const float ratio = 0.08838834764831845f;  // 1/sqrt(128)
    #pragma unroll
    for (int r = 0; r < 4; r++) {
        int rid = rowbase + r0 + r;
        int b = rid >> 15;           // / (L*H) = /32768
        int l = (rid >> 3) & 4095;
        int h = rid & 7;
        size_t off = ((size_t)(b * 8 + h) * Lc + l) * Mc;
        #pragma unroll
        for (int i = 0; i < 4; i++) {
            float val = acc[r][i] * ratio;
            val = (val > 0.f ? val : 0.f) + 1e-3f;
            outp[off + mg + 32 * i] = val;
        }
    }
}

// ---------------------------------------------------------------------------
// Kernel 2: per-chunk S = K_c^T V_c (stored d-major) and z = sum_k.
// grid 1024 = bh*64 + c, 256 threads.
// ---------------------------------------------------------------------------
__global__ void chunk_kernel(const float* __restrict__ vg)
{
    __shared__ float k_s[64 * 128];  // [c][m]
    __shared__ float v_s[64 * 64];   // [c][d]

    int tid = threadIdx.x;
    int bh  = blockIdx.x >> 6;
    int c   = blockIdx.x & 63;
    int b = bh >> 3, h = bh & 7;

    // load K chunk (contiguous 8192 floats)
    const float4* kp4 = (const float4*)&g_kp[((size_t)bh * Lc + c * 64) * Mc];
    float4* ks4 = (float4*)k_s;
    #pragma unroll
    for (int t = 0; t < 8; t++) ks4[tid + t * 256] = kp4[tid + t * 256];

    // load V chunk (row stride H*D = 512 floats)
    #pragma unroll
    for (int t = tid; t < 1024; t += 256) {
        int row = t >> 4, col = t & 15;
        int l = c * 64 + row;
        const float4* src = (const float4*)(vg + (((size_t)b * Lc + l) * Hc + h) * Dc);
        ((float4*)(v_s + row * 64))[col] = src[col];
    }
    __syncthreads();

    int mg = tid & 31, dg = tid >> 5;
    int m0 = mg * 4, d0 = dg * 8;
    float acc[4][8];
    #pragma unroll
    for (int i = 0; i < 4; i++)
        #pragma unroll
        for (int j = 0; j < 8; j++) acc[i][j] = 0.f;

    #pragma unroll 4
    for (int cc = 0; cc < 64; cc++) {
        float4 kv = *(const float4*)&k_s[cc * 128 + m0];
        float4 v0 = *(const float4*)&v_s[cc * 64 + d0];
        float4 v1 = *(const float4*)&v_s[cc * 64 + d0 + 4];
        float kk[4] = {kv.x, kv.y, kv.z, kv.w};
        float vv[8] = {v0.x, v0.y, v0.z, v0.w, v1.x, v1.y, v1.z, v1.w};
        #pragma unroll
        for (int i = 0; i < 4; i++)
            #pragma unroll
            for (int j = 0; j < 8; j++)
                acc[i][j] = fmaf(kk[i], vv[j], acc[i][j]);
    }

    // store S d-major: [d][m] -> coalesced float4 over m
    float* Sp = &g_state[(size_t)blockIdx.x * (Dc * Mc)];
    #pragma unroll
    for (int j = 0; j < 8; j++) {
        float4 w = make_float4(acc[0][j], acc[1][j], acc[2][j], acc[3][j]);
        *(float4*)&Sp[(d0 + j) * Mc + m0] = w;
    }

    // z[m]
    if (tid < 128) {
        float z = 0.f;
        #pragma unroll 8
        for (int cc = 0; cc < 64; cc++) z += k_s[cc * 128 + tid];
        g_ksum[(size_t)blockIdx.x * Mc + tid] = z;
    }
}

// ---------------------------------------------------------------------------
// Kernel 3: exclusive prefix over chunks (in place). grid 512 = bh*32 + slice.
// ---------------------------------------------------------------------------
__global__ void prefix_kernel()
{
    int bh    = blockIdx.x >> 5;
    int slice = blockIdx.x & 31;
    int e = slice * 256 + threadIdx.x;            // 0..8191
    size_t base = (size_t)bh * NCH * (Dc * Mc) + e;

    float acc = 0.f;
    #pragma unroll 1
    for (int c0 = 0; c0 < 64; c0 += 8) {
        float v[8];
        #pragma unroll
        for (int u = 0; u < 8; u++) v[u] = g_state[base + (size_t)(c0 + u) * (Dc * Mc)];
        #pragma unroll
        for (int u = 0; u < 8; u++) {
            g_state[base + (size_t)(c0 + u) * (Dc * Mc)] = acc;
            acc += v[u];
        }
    }

    if (slice == 0 && threadIdx.x < 128) {
        size_t kb = (size_t)bh * NCH * Mc + threadIdx.x;
        float a2 = 0.f;
        #pragma unroll 1
        for (int c = 0; c < 64; c++) {
            float t = g_ksum[kb + (size_t)c * Mc];
            g_ksum[kb + (size_t)c * Mc] = a2;
            a2 += t;
        }
    }
}

// ---------------------------------------------------------------------------
// Kernel 4: intra-chunk attention + state contribution + normalize.
// grid 1024 = bh*64 + c, 256 threads, dynamic smem.
// ---------------------------------------------------------------------------
#define QP 132
#define KTP 68
#define STP 68
#define VP 68
#define AP 65
#define SM4_FLOATS (64*QP + 128*KTP + 128*STP + 64*VP + 64*AP + 128 + 64)

__global__ void out_kernel(const float* __restrict__ vg, float* __restrict__ outg)
{
    extern __shared__ float sm[];
    float* q_s  = sm;                    // [i][m] pitch 132
    float* kT   = q_s + 64 * QP;         // [m][j] pitch 68
    float* st   = kT + 128 * KTP;        // [m][d] pitch 68
    float* v_s  = st + 128 * STP;        // [j][d] pitch 68
    float* a_s  = v_s + 64 * VP;         // [i][j] pitch 65
    float* ks_s = a_s + 64 * AP;         // [m]
    float* den_s = ks_s + 128;           // [i]

    int tid = threadIdx.x;
    int bh  = blockIdx.x >> 6;
    int c   = blockIdx.x & 63;
    int b = bh >> 3, h = bh & 7;

    // --- loads ---
    const float4* qsrc = (const float4*)&g_qp[((size_t)bh * Lc + c * 64) * Mc];
    const float4* ksrc = (const float4*)&g_kp[((size_t)bh * Lc + c * 64) * Mc];
    const float4* ssrc = (const float4*)&g_state[(size_t)blockIdx.x * (Dc * Mc)];

    #pragma unroll
    for (int t = tid; t < 2048; t += 256) {           // Q: direct copy (pitch 132)
        float4 w = qsrc[t];
        int row = t >> 5, col = (t & 31) * 4;
        *(float4*)&q_s[row * QP + col] = w;
    }
    #pragma unroll
    for (int t = tid; t < 2048; t += 256) {           // K: transpose to [m][j]
        float4 w = ksrc[t];
        int row = t >> 5;          // j (chunk position)
        int m0 = (t & 31) * 4;
        kT[(m0 + 0) * KTP + row] = w.x;
        kT[(m0 + 1) * KTP + row] = w.y;
        kT[(m0 + 2) * KTP + row] = w.z;
        kT[(m0 + 3) * KTP + row] = w.w;
    }
    #pragma unroll
    for (int t = tid; t < 2048; t += 256) {           // state: [d][m] global -> [m][d] smem
        float4 w = ssrc[t];
        int d = t >> 5;
        int m0 = (t & 31) * 4;
        st[(m0 + 0) * STP + d] = w.x;
        st[(m0 + 1) * STP + d] = w.y;
        st[(m0 + 2) * STP + d] = w.z;
        st[(m0 + 3) * STP + d] = w.w;
    }
    #pragma unroll
    for (int t = tid; t < 1024; t += 256) {           // V
        int row = t >> 4, col = t & 15;
        int l = c * 64 + row;
        const float4* src = (const float4*)(vg + (((size_t)b * Lc + l) * Hc + h) * Dc);
        *(float4*)&v_s[row * VP + col * 4] = src[col];
    }
    if (tid < 128) ks_s[tid] = g_ksum[(size_t)blockIdx.x * Mc + tid];
    __syncthreads();

    // --- phase 1: A = Q K^T (masked) ---
    {
        int jg = tid & 15, ig = tid >> 4;
        int i0 = ig * 4, j0 = jg * 4;
        float a[4][4];
        #pragma unroll
        for (int x = 0; x < 4; x++)
            #pragma unroll
            for (int y = 0; y < 4; y++) a[x][y] = 0.f;

        if (j0 <= i0 + 3) {
            #pragma unroll 4
            for (int m = 0; m < 128; m++) {
                float4 kv = *(const float4*)&kT[m * KTP + j0];
                float q0 = q_s[(i0 + 0) * QP + m];
                float q1 = q_s[(i0 + 1) * QP + m];
                float q2 = q_s[(i0 + 2) * QP + m];
                float q3 = q_s[(i0 + 3) * QP + m];
                a[0][0] = fmaf(q0, kv.x, a[0][0]); a[0][1] = fmaf(q0, kv.y, a[0][1]);
                a[0][2] = fmaf(q0, kv.z, a[0][2]); a[0][3] = fmaf(q0, kv.w, a[0][3]);
                a[1][0] = fmaf(q1, kv.x, a[1][0]); a[1][1] = fmaf(q1, kv.y, a[1][1]);
                a[1][2] = fmaf(q1, kv.z, a[1][2]); a[1][3] = fmaf(q1, kv.w, a[1][3]);
                a[2][0] = fmaf(q2, kv.x, a[2][0]); a[2][1] = fmaf(q2, kv.y, a[2][1]);
                a[2][2] = fmaf(q2, kv.z, a[2][2]); a[2][3] = fmaf(q2, kv.w, a[2][3]);
                a[3][0] = fmaf(q3, kv.x, a[3][0]); a[3][1] = fmaf(q3, kv.y, a[3][1]);
                a[3][2] = fmaf(q3, kv.z, a[3][2]); a[3][3] = fmaf(q3, kv.w, a[3][3]);
            }
        }
        #pragma unroll
        for (int x = 0; x < 4; x++) {
            int i = i0 + x;
            #pragma unroll
            for (int y = 0; y < 4; y++) {
                int j = j0 + y;
                a_s[i * AP + j] = (j <= i) ? a[x][y] : 0.f;
            }
        }
    }
    __syncthreads();

    // --- phase 2: num = Q*state + A*V, den, normalize ---
    int dg = tid & 7, igp = tid >> 3;
    int d0 = dg * 8, i0p = igp * 2;

    float num[2][8];
    #pragma unroll
    for (int r = 0; r < 2; r++)
        #pragma unroll
        for (int j = 0; j < 8; j++) num[r][j] = 0.f;

    #pragma unroll 2
    for (int m = 0; m < 128; m++) {
        float q0 = q_s[i0p * QP + m];
        float q1 = q_s[(i0p + 1) * QP + m];
        float4 s0 = *(const float4*)&st[m * STP + d0];
        float4 s1 = *(const float4*)&st[m * STP + d0 + 4];
        float ss[8] = {s0.x, s0.y, s0.z, s0.w, s1.x, s1.y, s1.z, s1.w};
        #pragma unroll
        for (int j = 0; j < 8; j++) num[0][j] = fmaf(q0, ss[j], num[0][j]);
        #pragma unroll
        for (int j = 0; j < 8; j++) num[1][j] = fmaf(q1, ss[j], num[1][j]);
    }

    int jmax = i0p + 1;
    #pragma unroll 2
    for (int j = 0; j <= jmax; j++) {
        float a0 = a_s[i0p * AP + j];
        float a1 = a_s[(i0p + 1) * AP + j];
        float4 v0 = *(const float4*)&v_s[j * VP + d0];
        float4 v1 = *(const float4*)&v_s[j * VP + d0 + 4];
        float vv[8] = {v0.x, v0.y, v0.z, v0.w, v1.x, v1.y, v1.z, v1.w};
        #pragma unroll
        for (int jj = 0; jj < 8; jj++) num[0][jj] = fmaf(a0, vv[jj], num[0][jj]);
        #pragma unroll
        for (int jj = 0; jj < 8; jj++) num[1][jj] = fmaf(a1, vv[jj], num[1][jj]);
    }

    if (tid < 64) {
        int i = tid;
        float dd = 0.f;
        #pragma unroll 4
        for (int m = 0; m < 128; m++) dd = fmaf(q_s[i * QP + m], ks_s[m], dd);
        for (int j = 0; j <= i; j++) dd += a_s[i * AP + j];
        den_s[i] = dd;
    }
    __syncthreads();

    #pragma unroll
    for (int r = 0; r < 2; r++) {
        int i = i0p + r;
        int l = c * 64 + i;
        float inv = __fdividef(1.f, den_s[i]);
        float* orow = outg + (((size_t)b * Lc + l) * Hc + h) * Dc;
        float4 o0 = make_float4(num[r][0] * inv, num[r][1] * inv, num[r][2] * inv, num[r][3] * inv);
        float4 o1 = make_float4(num[r][4] * inv, num[r][5] * inv, num[r][6] * inv, num[r][7] * inv);
        *(float4*)&orow[d0]     = o0;
        *(float4*)&orow[d0 + 4] = o1;
    }
}

// ---------------------------------------------------------------------------
extern "C" void kernel_launch(void* const* d_in, const int* in_sizes, int n_in,
                              void* d_out, int out_size)
{
    const float* q    = (const float*)d_in[0];
    const float* k    = (const float*)d_in[1];
    const float* v    = (const float*)d_in[2];
    const float* proj = (const float*)d_in[3];
    float* out = (float*)d_out;

    // No static guard (harness forbids call-count-dependent behavior).
    // cudaFuncSetAttribute is not a stream operation; safe during capture.
    cudaFuncSetAttribute(out_kernel, cudaFuncAttributeMaxDynamicSharedMemorySize,
                         SM4_FLOATS * (int)sizeof(float));

    proj_kernel<<<dim3(NROWS / 32, 2), 256>>>(q, k, proj);
    chunk_kernel<<<BH * NCH, 256>>>(v);
    prefix_kernel<<<BH * 32, 256>>>();
    out_kernel<<<BH * NCH, 256, SM4_FLOATS * (int)sizeof(float)>>>(v, out);
}